// round 4
// baseline (speedup 1.0000x reference)
#include <cuda_runtime.h>

// Problem constants (fixed by the reference).
constexpr int NN = 100000;   // nodes
constexpr int NE = 1600000;  // edges
constexpr int F1 = 64;       // layer-1 out features (== Fin)
constexpr int F2 = 32;       // layer-2 out features
constexpr int NB = (NN + 255) / 256;  // 391 scan blocks

// Scratch (device globals — no runtime allocation allowed).
__device__ int   g_deg[NN];
__device__ int   g_off[NN + 1];
__device__ int   g_cur[NN];
__device__ int   g_bsum[NB];
__device__ int   g_src[NE];
__device__ int   g_dst[NE];
__device__ int   g_csr_src[NE];
__device__ float g_dinv[NN];
__device__ float g_hs1[(size_t)NN * F1];   // (x@W1) * dinv[row]
__device__ float g_hs2[(size_t)NN * F2];   // (h1@W2) * dinv[row]
__device__ int   g_is64;

// ---------------------------------------------------------------------------
// Detect int64 vs int32 edge_index (jax x64-flag dependent). For int64 LE with
// values < 2^31 all odd 32-bit words are zero; for int32 they are random ids.
__global__ void detect_dtype(const unsigned int* __restrict__ w) {
    __shared__ int cnt;
    if (threadIdx.x == 0) cnt = 0;
    __syncthreads();
    if (w[threadIdx.x * 2 + 1] != 0u) atomicAdd(&cnt, 1);
    __syncthreads();
    if (threadIdx.x == 0) g_is64 = (cnt == 0) ? 1 : 0;
}

__global__ void zero_deg() {
    int i = blockIdx.x * blockDim.x + threadIdx.x;
    if (i < NN) g_deg[i] = 0;
}

// Convert indices to int32 + integer degree histogram.
__global__ void prep_edges(const int* __restrict__ w) {
    int e = blockIdx.x * blockDim.x + threadIdx.x;
    if (e >= NE) return;
    int s, d;
    if (g_is64) {
        s = w[2 * e];
        d = w[2 * (NE + e)];
    } else {
        s = w[e];
        d = w[NE + e];
    }
    g_src[e] = s;
    g_dst[e] = d;
    atomicAdd(&g_deg[d], 1);
}

__global__ void finish_dinv() {
    int i = blockIdx.x * blockDim.x + threadIdx.x;
    if (i < NN) g_dinv[i] = rsqrtf((float)g_deg[i] + 2.0f);  // improved: +2
}

// ---------------------------------------------------------------------------
// 3-kernel exclusive scan of g_deg -> g_off (and g_cur copy).
__global__ void block_sum() {
    int i = blockIdx.x * 256 + threadIdx.x;
    int v = (i < NN) ? g_deg[i] : 0;
    int lane = threadIdx.x & 31, wid = threadIdx.x >> 5;
#pragma unroll
    for (int o = 16; o > 0; o >>= 1) v += __shfl_down_sync(0xffffffffu, v, o);
    __shared__ int ws[8];
    if (lane == 0) ws[wid] = v;
    __syncthreads();
    if (threadIdx.x == 0) {
        int s = 0;
#pragma unroll
        for (int k = 0; k < 8; k++) s += ws[k];
        g_bsum[blockIdx.x] = s;
    }
}

__global__ void scan_bsum() {  // 1 block, 512 threads, NB=391 entries
    __shared__ int s[512];
    int t = threadIdx.x;
    int orig = (t < NB) ? g_bsum[t] : 0;
    s[t] = orig;
    __syncthreads();
#pragma unroll
    for (int o = 1; o < 512; o <<= 1) {
        int v = (t >= o) ? s[t - o] : 0;
        __syncthreads();
        s[t] += v;
        __syncthreads();
    }
    if (t < NB) g_bsum[t] = s[t] - orig;  // exclusive
}

__global__ void scan_final() {
    int i = blockIdx.x * 256 + threadIdx.x;
    int v = (i < NN) ? g_deg[i] : 0;
    int lane = threadIdx.x & 31, wid = threadIdx.x >> 5;
    int x = v;
#pragma unroll
    for (int o = 1; o < 32; o <<= 1) {
        int y = __shfl_up_sync(0xffffffffu, x, o);
        if (lane >= o) x += y;
    }
    __shared__ int ws[8];
    if (lane == 31) ws[wid] = x;
    __syncthreads();
    if (threadIdx.x == 0) {
        int r = 0;
#pragma unroll
        for (int k = 0; k < 8; k++) { int t = ws[k]; ws[k] = r; r += t; }
    }
    __syncthreads();
    int off = g_bsum[blockIdx.x] + ws[wid] + (x - v);  // exclusive
    if (i < NN) {
        g_off[i] = off;
        g_cur[i] = off;
        if (i == NN - 1) g_off[NN] = off + v;
    }
}

__global__ void fill_csr() {
    int e = blockIdx.x * blockDim.x + threadIdx.x;
    if (e >= NE) return;
    int pos = atomicAdd(&g_cur[g_dst[e]], 1);
    g_csr_src[pos] = g_src[e];
}

// ---------------------------------------------------------------------------
// GEMM: out[row, :] = (x[row, :] @ W) * dinv[row].  K = 64 fixed.
template <int FOUT>
__global__ void gemm_scale(const float* __restrict__ x, const float* __restrict__ W) {
    constexpr int K = 64, ROWS = 32, XP = K + 4;
    constexpr int TJ = FOUT / 4;
    constexpr int NT = (ROWS / 4) * TJ;
    __shared__ float xs[ROWS][XP];
    __shared__ float ws[K][FOUT];
    float* out = (FOUT == 64) ? g_hs1 : g_hs2;

    int tid = threadIdx.x;
    int row0 = blockIdx.x * ROWS;

    for (int f4 = tid; f4 < ROWS * K / 4; f4 += NT) {
        int r = f4 >> 4, kc = f4 & 15;
        float4 v = ((const float4*)(x + (size_t)(row0 + r) * K))[kc];
        *(float4*)&xs[r][kc * 4] = v;
    }
    for (int f4 = tid; f4 < K * FOUT / 4; f4 += NT)
        ((float4*)ws)[f4] = ((const float4*)W)[f4];
    __syncthreads();

    int j = tid % TJ;
    int i = tid / TJ;
    float acc[4][4] = {};
#pragma unroll 8
    for (int k = 0; k < K; k++) {
        float av[4];
#pragma unroll
        for (int r = 0; r < 4; r++) av[r] = xs[i * 4 + r][k];
        float4 b = *(const float4*)&ws[k][j * 4];
#pragma unroll
        for (int r = 0; r < 4; r++) {
            acc[r][0] = fmaf(av[r], b.x, acc[r][0]);
            acc[r][1] = fmaf(av[r], b.y, acc[r][1]);
            acc[r][2] = fmaf(av[r], b.z, acc[r][2]);
            acc[r][3] = fmaf(av[r], b.w, acc[r][3]);
        }
    }
#pragma unroll
    for (int r = 0; r < 4; r++) {
        int row = row0 + i * 4 + r;
        float dv = g_dinv[row];
        float4 o = make_float4(acc[r][0] * dv, acc[r][1] * dv,
                               acc[r][2] * dv, acc[r][3] * dv);
        *(float4*)&out[(size_t)row * FOUT + j * 4] = o;
    }
}

// ---------------------------------------------------------------------------
// Pull aggregation, one warp per dst node, fused epilogue.
// F=64: each lane owns a float2 slice of the row.
__global__ void agg1(const float* __restrict__ b, float* __restrict__ feat) {
    int warp = (blockIdx.x * 256 + threadIdx.x) >> 5;
    int lane = threadIdx.x & 31;
    if (warp >= NN) return;
    int beg = g_off[warp], end = g_off[warp + 1];
    const float2* hs = (const float2*)g_hs1;
    float ax = 0.f, ay = 0.f;
    int i = beg;
    for (; i + 4 <= end; i += 4) {
        int s0 = g_csr_src[i], s1 = g_csr_src[i + 1];
        int s2 = g_csr_src[i + 2], s3 = g_csr_src[i + 3];
        float2 v0 = hs[s0 * 32 + lane];
        float2 v1 = hs[s1 * 32 + lane];
        float2 v2 = hs[s2 * 32 + lane];
        float2 v3 = hs[s3 * 32 + lane];
        ax += (v0.x + v1.x) + (v2.x + v3.x);
        ay += (v0.y + v1.y) + (v2.y + v3.y);
    }
    for (; i < end; i++) {
        float2 v = hs[g_csr_src[i] * 32 + lane];
        ax += v.x;
        ay += v.y;
    }
    float dv = g_dinv[warp];
    float2 h = hs[warp * 32 + lane];
    float2 bb = ((const float2*)b)[lane];
    float2 o;
    o.x = fmaxf(fmaf(dv, fmaf(2.f, h.x, ax), bb.x), 0.f);
    o.y = fmaxf(fmaf(dv, fmaf(2.f, h.y, ay), bb.y), 0.f);
    ((float2*)feat)[warp * 32 + lane] = o;
}

// F=32: each lane owns one float of the row.
__global__ void agg2(const float* __restrict__ b, float* __restrict__ out) {
    int warp = (blockIdx.x * 256 + threadIdx.x) >> 5;
    int lane = threadIdx.x & 31;
    if (warp >= NN) return;
    int beg = g_off[warp], end = g_off[warp + 1];
    const float* hs = g_hs2;
    float a = 0.f;
    int i = beg;
    for (; i + 4 <= end; i += 4) {
        int s0 = g_csr_src[i], s1 = g_csr_src[i + 1];
        int s2 = g_csr_src[i + 2], s3 = g_csr_src[i + 3];
        float v0 = hs[s0 * 32 + lane];
        float v1 = hs[s1 * 32 + lane];
        float v2 = hs[s2 * 32 + lane];
        float v3 = hs[s3 * 32 + lane];
        a += (v0 + v1) + (v2 + v3);
    }
    for (; i < end; i++) a += hs[g_csr_src[i] * 32 + lane];
    float dv = g_dinv[warp];
    float h = hs[warp * 32 + lane];
    out[warp * 32 + lane] = fmaf(dv, fmaf(2.f, h, a), b[lane]);
}

// ---------------------------------------------------------------------------
extern "C" void kernel_launch(void* const* d_in, const int* in_sizes, int n_in,
                              void* d_out, int out_size) {
    const float* x  = (const float*)d_in[0];
    const int*   ei = (const int*)d_in[1];
    const float* W1 = (const float*)d_in[2];
    const float* b1 = (const float*)d_in[3];
    const float* W2 = (const float*)d_in[4];
    const float* b2 = (const float*)d_in[5];

    float* out  = (float*)d_out;              // [N, 32]
    float* feat = out + (size_t)NN * F2;      // [N, 64] feature_map

    detect_dtype<<<1, 1024>>>((const unsigned int*)ei);
    zero_deg<<<NB, 256>>>();
    prep_edges<<<(NE + 255) / 256, 256>>>(ei);

    // CSR build
    block_sum<<<NB, 256>>>();
    scan_bsum<<<1, 512>>>();
    scan_final<<<NB, 256>>>();
    fill_csr<<<(NE + 255) / 256, 256>>>();
    finish_dinv<<<NB, 256>>>();

    // Layer 1
    gemm_scale<F1><<<NN / 32, 128>>>(x, W1);
    agg1<<<(NN * 32 + 255) / 256, 256>>>(b1, feat);

    // Layer 2 (reads h1 from the feature_map output region)
    gemm_scale<F2><<<NN / 32, 64>>>(feat, W2);
    agg2<<<(NN * 32 + 255) / 256, 256>>>(b2, out);
}

// round 7
// speedup vs baseline: 1.0475x; 1.0475x over previous
#include <cuda_runtime.h>

// Problem constants (fixed by the reference).
constexpr int NN = 100000;   // nodes
constexpr int NE = 1600000;  // edges
constexpr int F1 = 64;       // layer-1 out features (== Fin)
constexpr int F2 = 32;       // layer-2 out features
constexpr int NB = (NN + 255) / 256;   // 391 scan blocks
constexpr int GB1 = NN / 32;           // 3125 gemm blocks in fused kernel
constexpr int PB = NE / 256;           // 6250 prep blocks (128 thr x 2 edges)

// Scratch (device globals — no runtime allocation allowed).
// NOTE: device globals are ONLY referenced inside device code. Passing them
// as kernel arguments from host passes the host shadow address (silently
// "works" on GB300 ATS and corrupts results) — that was the R5/R6 bug.
__device__ int   g_deg[NN];
__device__ int   g_off[NN + 1];
__device__ int   g_cur[NN];
__device__ int   g_bsum[NB];
__device__ int   g_csr_src[NE];
__device__ float g_dinv[NN];
__device__ float g_h1[(size_t)NN * F1];    // raw x@W1 (NOT dinv-scaled)
__device__ float g_hs2[(size_t)NN * F2];   // (h1@W2) * dinv[row]
__device__ int   g_is64;

// ---------------------------------------------------------------------------
// Detect int64 vs int32 edge_index (jax x64-flag dependent). For int64 LE with
// values < 2^31 all odd 32-bit words are zero; for int32 they are random ids.
__global__ void detect_dtype(const unsigned int* __restrict__ w) {
    __shared__ int cnt;
    if (threadIdx.x == 0) cnt = 0;
    __syncthreads();
    if (w[threadIdx.x * 2 + 1] != 0u) atomicAdd(&cnt, 1);
    __syncthreads();
    if (threadIdx.x == 0) g_is64 = (cnt == 0) ? 1 : 0;
}

__global__ void zero_deg() {
    int i = blockIdx.x * blockDim.x + threadIdx.x;
    if (i < NN) g_deg[i] = 0;
}

// ---------------------------------------------------------------------------
// FUSED: blocks [0, GB1) -> raw gemm1 (h1 = x @ W1); blocks [GB1, GB1+PB) ->
// edge-degree histogram. Single kernel = capture-safe overlap of the two
// independent phases.
__global__ void fused_gemm1_prep(const float* __restrict__ x,
                                 const float* __restrict__ W,
                                 const int* __restrict__ w) {
    constexpr int K = 64, ROWS = 32, XP = K + 4, FOUT = F1;
    constexpr int NT = 128;
    __shared__ float xs[ROWS][XP];
    __shared__ float ws[K][FOUT];

    int tid = threadIdx.x;
    if (blockIdx.x >= GB1) {
        // ---- prep phase: degree histogram, 2 edges per thread ----
        int base = (blockIdx.x - GB1) * 256;
        int is64 = g_is64;
#pragma unroll
        for (int r = 0; r < 2; r++) {
            int e = base + r * 128 + tid;
            int d = is64 ? w[2 * (NE + e)] : w[NE + e];
            atomicAdd(&g_deg[d], 1);
        }
        return;
    }

    // ---- gemm phase: 32 rows, 4x4 micro-tile, raw (unscaled) output ----
    int row0 = blockIdx.x * ROWS;
    for (int f4 = tid; f4 < ROWS * K / 4; f4 += NT) {
        int r = f4 >> 4, kc = f4 & 15;
        float4 v = ((const float4*)(x + (size_t)(row0 + r) * K))[kc];
        *(float4*)&xs[r][kc * 4] = v;
    }
    for (int f4 = tid; f4 < K * FOUT / 4; f4 += NT)
        ((float4*)ws)[f4] = ((const float4*)W)[f4];
    __syncthreads();

    int j = tid % 16;
    int i = tid / 16;
    float acc[4][4] = {};
#pragma unroll 8
    for (int k = 0; k < K; k++) {
        float av[4];
#pragma unroll
        for (int r = 0; r < 4; r++) av[r] = xs[i * 4 + r][k];
        float4 b = *(const float4*)&ws[k][j * 4];
#pragma unroll
        for (int r = 0; r < 4; r++) {
            acc[r][0] = fmaf(av[r], b.x, acc[r][0]);
            acc[r][1] = fmaf(av[r], b.y, acc[r][1]);
            acc[r][2] = fmaf(av[r], b.z, acc[r][2]);
            acc[r][3] = fmaf(av[r], b.w, acc[r][3]);
        }
    }
#pragma unroll
    for (int r = 0; r < 4; r++) {
        int row = row0 + i * 4 + r;
        float4 o = make_float4(acc[r][0], acc[r][1], acc[r][2], acc[r][3]);
        *(float4*)&g_h1[(size_t)row * FOUT + j * 4] = o;
    }
}

// ---------------------------------------------------------------------------
// 3-kernel exclusive scan of g_deg -> g_off (+ g_cur copy, + dinv fused).
__global__ void block_sum() {
    int i = blockIdx.x * 256 + threadIdx.x;
    int v = (i < NN) ? g_deg[i] : 0;
    int lane = threadIdx.x & 31, wid = threadIdx.x >> 5;
#pragma unroll
    for (int o = 16; o > 0; o >>= 1) v += __shfl_down_sync(0xffffffffu, v, o);
    __shared__ int ws[8];
    if (lane == 0) ws[wid] = v;
    __syncthreads();
    if (threadIdx.x == 0) {
        int s = 0;
#pragma unroll
        for (int k = 0; k < 8; k++) s += ws[k];
        g_bsum[blockIdx.x] = s;
    }
}

__global__ void scan_bsum() {  // 1 block, 512 threads, NB=391 entries
    __shared__ int s[512];
    int t = threadIdx.x;
    int orig = (t < NB) ? g_bsum[t] : 0;
    s[t] = orig;
    __syncthreads();
#pragma unroll
    for (int o = 1; o < 512; o <<= 1) {
        int v = (t >= o) ? s[t - o] : 0;
        __syncthreads();
        s[t] += v;
        __syncthreads();
    }
    if (t < NB) g_bsum[t] = s[t] - orig;  // exclusive
}

__global__ void scan_final() {
    int i = blockIdx.x * 256 + threadIdx.x;
    int v = (i < NN) ? g_deg[i] : 0;
    int lane = threadIdx.x & 31, wid = threadIdx.x >> 5;
    int x = v;
#pragma unroll
    for (int o = 1; o < 32; o <<= 1) {
        int y = __shfl_up_sync(0xffffffffu, x, o);
        if (lane >= o) x += y;
    }
    __shared__ int ws[8];
    if (lane == 31) ws[wid] = x;
    __syncthreads();
    if (threadIdx.x == 0) {
        int r = 0;
#pragma unroll
        for (int k = 0; k < 8; k++) { int t = ws[k]; ws[k] = r; r += t; }
    }
    __syncthreads();
    int off = g_bsum[blockIdx.x] + ws[wid] + (x - v);  // exclusive
    if (i < NN) {
        g_off[i] = off;
        g_cur[i] = off;
        g_dinv[i] = rsqrtf((float)v + 2.0f);  // improved self-loops: +2
        if (i == NN - 1) g_off[NN] = off + v;
    }
}

// Reads the raw edge list again (dtype-aware) — no staged src/dst arrays.
__global__ void fill_csr(const int* __restrict__ w) {
    int e = blockIdx.x * blockDim.x + threadIdx.x;
    if (e >= NE) return;
    int s, d;
    if (g_is64) {
        s = w[2 * e];
        d = w[2 * (NE + e)];
    } else {
        s = w[e];
        d = w[NE + e];
    }
    int pos = atomicAdd(&g_cur[d], 1);
    g_csr_src[pos] = s;
}

// ---------------------------------------------------------------------------
// GEMM layer 2: g_hs2[row,:] = (x[row,:] @ W) * dinv[row].  K=64, FOUT=32.
// Output written to the device symbol DIRECTLY (no host-passed pointer).
__global__ void gemm2_scale(const float* __restrict__ x,
                            const float* __restrict__ W) {
    constexpr int K = 64, ROWS = 32, XP = K + 4, FOUT = F2;
    constexpr int TJ = FOUT / 4;          // 8
    constexpr int NT = (ROWS / 4) * TJ;   // 64 threads
    __shared__ float xs[ROWS][XP];
    __shared__ float ws[K][FOUT];

    int tid = threadIdx.x;
    int row0 = blockIdx.x * ROWS;

    for (int f4 = tid; f4 < ROWS * K / 4; f4 += NT) {
        int r = f4 >> 4, kc = f4 & 15;
        float4 v = ((const float4*)(x + (size_t)(row0 + r) * K))[kc];
        *(float4*)&xs[r][kc * 4] = v;
    }
    for (int f4 = tid; f4 < K * FOUT / 4; f4 += NT)
        ((float4*)ws)[f4] = ((const float4*)W)[f4];
    __syncthreads();

    int j = tid % TJ;
    int i = tid / TJ;
    float acc[4][4] = {};
#pragma unroll 8
    for (int k = 0; k < K; k++) {
        float av[4];
#pragma unroll
        for (int r = 0; r < 4; r++) av[r] = xs[i * 4 + r][k];
        float4 b = *(const float4*)&ws[k][j * 4];
#pragma unroll
        for (int r = 0; r < 4; r++) {
            acc[r][0] = fmaf(av[r], b.x, acc[r][0]);
            acc[r][1] = fmaf(av[r], b.y, acc[r][1]);
            acc[r][2] = fmaf(av[r], b.z, acc[r][2]);
            acc[r][3] = fmaf(av[r], b.w, acc[r][3]);
        }
    }
#pragma unroll
    for (int r = 0; r < 4; r++) {
        int row = row0 + i * 4 + r;
        float dv = g_dinv[row];
        float4 o = make_float4(acc[r][0] * dv, acc[r][1] * dv,
                               acc[r][2] * dv, acc[r][3] * dv);
        *(float4*)&g_hs2[(size_t)row * FOUT + j * 4] = o;
    }
}

// ---------------------------------------------------------------------------
// Pull aggregation layer 1: one warp per dst node, fused epilogue.
// h1 is RAW: a = sum dinv[s]*h1[s]; out = relu(dv*(a + 2*dv*h_self) + b).
__global__ void agg1(const float* __restrict__ b, float* __restrict__ feat) {
    int warp = (blockIdx.x * 256 + threadIdx.x) >> 5;
    int lane = threadIdx.x & 31;
    if (warp >= NN) return;
    int beg = g_off[warp], end = g_off[warp + 1];
    const float2* __restrict__ hs = (const float2*)g_h1;
    float ax = 0.f, ay = 0.f;
    int i = beg;
    for (; i + 4 <= end; i += 4) {
        int s0 = g_csr_src[i], s1 = g_csr_src[i + 1];
        int s2 = g_csr_src[i + 2], s3 = g_csr_src[i + 3];
        float d0 = g_dinv[s0], d1 = g_dinv[s1];
        float d2 = g_dinv[s2], d3 = g_dinv[s3];
        float2 v0 = hs[s0 * 32 + lane];
        float2 v1 = hs[s1 * 32 + lane];
        float2 v2 = hs[s2 * 32 + lane];
        float2 v3 = hs[s3 * 32 + lane];
        ax = fmaf(d0, v0.x, ax); ay = fmaf(d0, v0.y, ay);
        ax = fmaf(d1, v1.x, ax); ay = fmaf(d1, v1.y, ay);
        ax = fmaf(d2, v2.x, ax); ay = fmaf(d2, v2.y, ay);
        ax = fmaf(d3, v3.x, ax); ay = fmaf(d3, v3.y, ay);
    }
    for (; i < end; i++) {
        int s = g_csr_src[i];
        float d = g_dinv[s];
        float2 v = hs[s * 32 + lane];
        ax = fmaf(d, v.x, ax);
        ay = fmaf(d, v.y, ay);
    }
    float dv = g_dinv[warp];
    float2 h = hs[warp * 32 + lane];
    float2 bb = ((const float2*)b)[lane];
    float tdv = 2.f * dv;
    float2 o;
    o.x = fmaxf(fmaf(dv, fmaf(tdv, h.x, ax), bb.x), 0.f);
    o.y = fmaxf(fmaf(dv, fmaf(tdv, h.y, ay), bb.y), 0.f);
    ((float2*)feat)[warp * 32 + lane] = o;
}

// Layer 2: g_hs2 pre-scaled by dinv[row]; each lane owns one float of the row.
__global__ void agg2(const float* __restrict__ b, float* __restrict__ out) {
    int warp = (blockIdx.x * 256 + threadIdx.x) >> 5;
    int lane = threadIdx.x & 31;
    if (warp >= NN) return;
    int beg = g_off[warp], end = g_off[warp + 1];
    const float* __restrict__ hs = g_hs2;
    float a = 0.f;
    int i = beg;
    for (; i + 4 <= end; i += 4) {
        int s0 = g_csr_src[i], s1 = g_csr_src[i + 1];
        int s2 = g_csr_src[i + 2], s3 = g_csr_src[i + 3];
        float v0 = hs[s0 * 32 + lane];
        float v1 = hs[s1 * 32 + lane];
        float v2 = hs[s2 * 32 + lane];
        float v3 = hs[s3 * 32 + lane];
        a += (v0 + v1) + (v2 + v3);
    }
    for (; i < end; i++) a += hs[g_csr_src[i] * 32 + lane];
    float dv = g_dinv[warp];
    float h = hs[warp * 32 + lane];
    out[warp * 32 + lane] = fmaf(dv, fmaf(2.f, h, a), b[lane]);
}

// ---------------------------------------------------------------------------
extern "C" void kernel_launch(void* const* d_in, const int* in_sizes, int n_in,
                              void* d_out, int out_size) {
    const float* x  = (const float*)d_in[0];
    const int*   ei = (const int*)d_in[1];
    const float* W1 = (const float*)d_in[2];
    const float* b1 = (const float*)d_in[3];
    const float* W2 = (const float*)d_in[4];
    const float* b2 = (const float*)d_in[5];

    float* out  = (float*)d_out;              // [N, 32]
    float* feat = out + (size_t)NN * F2;      // [N, 64] feature_map

    detect_dtype<<<1, 1024>>>((const unsigned int*)ei);
    zero_deg<<<NB, 256>>>();

    // gemm1 (raw h1) overlapped with edge-degree histogram in ONE kernel.
    fused_gemm1_prep<<<GB1 + PB, 128>>>(x, W1, ei);

    // CSR build (dinv fused into scan_final).
    block_sum<<<NB, 256>>>();
    scan_bsum<<<1, 512>>>();
    scan_final<<<NB, 256>>>();
    fill_csr<<<(NE + 255) / 256, 256>>>(ei);

    // Layer 1 aggregation (dinv[src]-weighted gather over raw h1).
    agg1<<<(NN * 32 + 255) / 256, 256>>>(b1, feat);

    // Layer 2 (reads h1 activations from the feature_map output region).
    gemm2_scale<<<NN / 32, 64>>>(feat, W2);
    agg2<<<(NN * 32 + 255) / 256, 256>>>(b2, out);
}